// round 3
// baseline (speedup 1.0000x reference)
#include <cuda_runtime.h>
#include <math.h>

#define T_ 24
#define B_ 64
#define I_ 128
#define H_ 256
#define R_ 64
#define HR 320
#define NBLK 148
#define NTHR 512
#define ISUB 7
#define BSUB 16
#define LN_EPS 1e-5f

// ---- smem layout (float offsets) ----
#define SM_TE   0          // 112*256 = 28672
#define SM_RA   28672      // 7*256 = 1792
#define SM_SE   30464
#define SM_SU   32256
#define SM_HI   34048
#define SM_LO   35840      // ends 37632
#define SM_V    37632      // 256
#define SM_WH   37888      // 320
#define SM_SH   38208      // 256
#define SM_SU2  38464      // 64
#define SM_RED  38528      // 64
#define SM_XB   38592      // 24*128 = 3072
#define SM_WXR  41664      // 24*320 = 7680
#define SM_SV   49344      // 256
#define SM_TOTAL_FLOATS 49600
#define SM_BYTES (SM_TOTAL_FLOATS*4)

// ---- global scratch ----
__device__ float g_Wx[T_*B_*HR];
__device__ float g_hbuf[2*B_*H_];
__device__ float g_tebuf[2*B_*H_];
__device__ float g_mod[B_*H_];
__device__ float g_z[B_*H_];
__device__ unsigned g_bar_count = 0;
__device__ volatile unsigned g_bar_gen = 0;

__device__ __forceinline__ float sigmoidf(float x) { return 1.f / (1.f + expf(-x)); }

__device__ __forceinline__ void grid_barrier() {
    __threadfence();
    __syncthreads();
    if (threadIdx.x == 0) {
        unsigned g = g_bar_gen;
        if (atomicAdd(&g_bar_count, 1u) == NBLK - 1u) {
            g_bar_count = 0;          // safe: others can't re-arrive until gen bumps
            __threadfence();
            g_bar_gen = g + 1u;
        } else {
            while (g_bar_gen == g) { }
        }
        __threadfence();
    }
    __syncthreads();
}

__global__ __launch_bounds__(NTHR, 1)
void sgru_persistent(const float* __restrict__ x,
                     const float* __restrict__ h0,
                     const float* __restrict__ v0,
                     const float* __restrict__ dU0,
                     const float* __restrict__ te0,
                     const float* __restrict__ tE0,
                     const float* __restrict__ x2h_w,
                     const float* __restrict__ x2h_b,
                     const float* __restrict__ h2h_w,
                     const float* __restrict__ h2h_b,
                     const float* __restrict__ lnx_g,
                     const float* __restrict__ lnx_b,
                     const float* __restrict__ lnh_g,
                     const float* __restrict__ lnh_b,
                     const float* __restrict__ alpha,
                     const float* __restrict__ mod2h,
                     const float* __restrict__ tau_v,
                     const float* __restrict__ tau_U,
                     const float* __restrict__ tau_E,
                     float* __restrict__ outp) {
    extern __shared__ float sm[];
    const int bid = blockIdx.x;
    const int tid = threadIdx.x;
    const int i_grp = bid >> 2;
    const int b_grp = bid & 3;
    const int w = tid >> 5;
    const int lane = tid & 31;

    float* o_v   = outp;
    float* o_h   = outp + 16384;
    float* o_dU  = outp + 32768;
    float* o_te  = outp + 4227072;
    float* o_tE  = outp + 4243456;
    float* o_out = outp + 8437760;

    // ============ PROLOGUE ============
    // per-(i,j) constants -> smem (time-invariant)
    for (int idx = tid; idx < ISUB * H_; idx += NTHR) {
        int isub = idx >> 8, j = idx & 255;
        int i = i_grp * ISUB + isub;
        float ra = 0.f, se = 0.f, su = 0.f, hi = 0.f, lo = 0.f;
        if (i < H_) {
            int ij = i * H_ + j;
            ra = fmaxf(alpha[ij], 0.f);
            su = sigmoidf(tau_U[ij]);
            se = sigmoidf(tau_E[ij]);
            float wv = h2h_w[ij];
            float den = ra + 1e-8f;
            hi = fmaxf(1.f - wv, 0.f) / den;
            lo = -fmaxf(1.f + wv, 0.f) / den;
        }
        sm[SM_RA + idx] = ra; sm[SM_SE + idx] = se; sm[SM_SU + idx] = su;
        sm[SM_HI + idx] = hi; sm[SM_LO + idx] = lo;
    }
    // tE0 -> smem
    for (int idx = tid; idx < BSUB * ISUB * H_; idx += NTHR) {
        int row = idx >> 8;
        int wsub = row / ISUB, isub = row - wsub * ISUB;
        int i = i_grp * ISUB + isub;
        int b = b_grp * BSUB + wsub;
        int j = idx & 255;
        sm[SM_TE + idx] = (i < H_) ? tE0[(b * H_ + i) * H_ + j] : 0.f;
    }
    if (bid < B_ && tid < H_) sm[SM_SV + tid] = sigmoidf(tau_v[tid]);
    __syncthreads();

    // dU0 -> registers; z0 = sum_j ra*dU0*h0
    const int myb = b_grp * BSUB + w;
    float dUr[ISUB][8];
    {
        float h0v[8];
#pragma unroll
        for (int m = 0; m < 8; m++) h0v[m] = h0[myb * H_ + lane + 32 * m];
#pragma unroll
        for (int r = 0; r < ISUB; r++) {
            int i = i_grp * ISUB + r;
            if (i < H_) {
                float acc = 0.f;
#pragma unroll
                for (int m = 0; m < 8; m++) {
                    float d = dU0[(myb * H_ + i) * H_ + lane + 32 * m];
                    dUr[r][m] = d;
                    acc += sm[SM_RA + r * H_ + lane + 32 * m] * d * h0v[m];
                }
#pragma unroll
                for (int o = 16; o > 0; o >>= 1) acc += __shfl_xor_sync(0xffffffffu, acc, o);
                if (lane == 0) __stcg(&g_z[myb * H_ + i], acc);
            } else {
#pragma unroll
                for (int m = 0; m < 8; m++) dUr[r][m] = 0.f;
            }
        }
    }

    // small-role blocks: copy state, precompute Wx for all t
    if (bid < B_) {
        if (tid < H_) {
            __stcg(&g_hbuf[bid * H_ + tid], h0[bid * H_ + tid]);
            __stcg(&g_tebuf[bid * H_ + tid], te0[bid * H_ + tid]);
            sm[SM_V + tid] = v0[bid * H_ + tid];
        }
        for (int idx = tid; idx < T_ * I_; idx += NTHR)
            sm[SM_XB + idx] = x[(idx >> 7) * (B_ * I_) + bid * I_ + (idx & 127)];
        __syncthreads();
        // GEMM: 64 groups of 8 lanes, 5 outputs each, weights in regs, t inner
        {
            int g8 = tid >> 3, l8 = tid & 7;
#pragma unroll
            for (int ko = 0; ko < 5; ko++) {
                int k = g8 + 64 * ko;
                const float4* wr = (const float4*)(x2h_w + k * I_ + l8 * 16);
                float4 wv0 = wr[0], wv1 = wr[1], wv2 = wr[2], wv3 = wr[3];
                float bias = x2h_b[k];
                for (int tt = 0; tt < T_; tt++) {
                    const float* xb = &sm[SM_XB + tt * I_ + l8 * 16];
                    float acc = wv0.x*xb[0] + wv0.y*xb[1] + wv0.z*xb[2] + wv0.w*xb[3]
                              + wv1.x*xb[4] + wv1.y*xb[5] + wv1.z*xb[6] + wv1.w*xb[7]
                              + wv2.x*xb[8] + wv2.y*xb[9] + wv2.z*xb[10]+ wv2.w*xb[11]
                              + wv3.x*xb[12]+ wv3.y*xb[13]+ wv3.z*xb[14]+ wv3.w*xb[15];
                    acc += __shfl_xor_sync(0xffffffffu, acc, 4);
                    acc += __shfl_xor_sync(0xffffffffu, acc, 2);
                    acc += __shfl_xor_sync(0xffffffffu, acc, 1);
                    if (l8 == 0) sm[SM_WXR + tt * HR + k] = acc + bias;
                }
            }
        }
        __syncthreads();
        // LN per t (warp per row)
        for (int tt = w; tt < T_; tt += 16) {
            float vv[10]; float s = 0.f, s2 = 0.f;
#pragma unroll
            for (int e = 0; e < 10; e++) {
                vv[e] = sm[SM_WXR + tt * HR + lane + 32 * e];
                s += vv[e]; s2 += vv[e] * vv[e];
            }
#pragma unroll
            for (int o = 16; o > 0; o >>= 1) {
                s  += __shfl_xor_sync(0xffffffffu, s,  o);
                s2 += __shfl_xor_sync(0xffffffffu, s2, o);
            }
            float mu = s * (1.f / HR);
            float inv = rsqrtf(s2 * (1.f / HR) - mu * mu + LN_EPS);
#pragma unroll
            for (int e = 0; e < 10; e++) {
                int k = lane + 32 * e;
                g_Wx[(tt * B_ + bid) * HR + k] = (vv[e] - mu) * inv * lnx_g[k] + lnx_b[k];
            }
        }
    }
    grid_barrier();

    // ============ TIME LOOP ============
    for (int t = 0; t < T_; t++) {
        const float* hbO = g_hbuf  + (t & 1) * (B_ * H_);
        float*       hbN = g_hbuf  + ((t + 1) & 1) * (B_ * H_);
        const float* teO = g_tebuf + (t & 1) * (B_ * H_);
        float*       teN = g_tebuf + ((t + 1) & 1) * (B_ * H_);

        // ---- small phase (blocks 0..63; block == batch) ----
        if (bid < B_) {
            if (tid < H_) sm[SM_SH + tid] = __ldcg(&hbO[bid * H_ + tid]);
            __syncthreads();
            int g8 = tid >> 3, l8 = tid & 7;
#pragma unroll
            for (int ko = 0; ko < 5; ko++) {
                int k = g8 + 64 * ko;
                const float4* wr = (const float4*)(h2h_w + k * H_ + l8 * 32);
                float acc = 0.f;
#pragma unroll
                for (int m = 0; m < 8; m++) {
                    float4 wv = wr[m];
                    const float* hh = &sm[SM_SH + l8 * 32 + m * 4];
                    acc += wv.x*hh[0] + wv.y*hh[1] + wv.z*hh[2] + wv.w*hh[3];
                }
                acc += __shfl_xor_sync(0xffffffffu, acc, 4);
                acc += __shfl_xor_sync(0xffffffffu, acc, 2);
                acc += __shfl_xor_sync(0xffffffffu, acc, 1);
                if (l8 == 0) sm[SM_WH + k] = acc + h2h_b[k];
            }
            __syncthreads();
            // block LN over 320
            float val = (tid < HR) ? sm[SM_WH + tid] : 0.f;
            float s = val, s2 = val * val;
#pragma unroll
            for (int o = 16; o > 0; o >>= 1) {
                s  += __shfl_xor_sync(0xffffffffu, s,  o);
                s2 += __shfl_xor_sync(0xffffffffu, s2, o);
            }
            if (lane == 0) { sm[SM_RED + w] = s; sm[SM_RED + 16 + w] = s2; }
            __syncthreads();
            if (w == 0) {
                float a  = (lane < 16) ? sm[SM_RED + lane] : 0.f;
                float a2 = (lane < 16) ? sm[SM_RED + 16 + lane] : 0.f;
#pragma unroll
                for (int o = 16; o > 0; o >>= 1) {
                    a  += __shfl_xor_sync(0xffffffffu, a,  o);
                    a2 += __shfl_xor_sync(0xffffffffu, a2, o);
                }
                if (lane == 0) { sm[SM_RED + 32] = a; sm[SM_RED + 33] = a2; }
            }
            __syncthreads();
            float mu = sm[SM_RED + 32] * (1.f / HR);
            float inv = rsqrtf(sm[SM_RED + 33] * (1.f / HR) - mu * mu + LN_EPS);
            float whv = 0.f, wxv = 0.f;
            if (tid < HR) {
                whv = (val - mu) * inv * lnh_g[tid] + lnh_b[tid];
                wxv = g_Wx[(t * B_ + bid) * HR + tid];
                if (tid >= H_) sm[SM_SU2 + tid - H_] = fmaxf(wxv + whv, 0.f);
            }
            __syncthreads();
            if (tid < H_) {
                float sv = sm[SM_SV + tid];
                float dv = wxv + whv + __ldcg(&g_z[bid * H_ + tid]);
                float vo = sm[SM_V + tid];
                float vn = vo + sv * (dv - vo);
                sm[SM_V + tid] = vn;
                float nh = fmaxf(vn, 0.f);
                __stcg(&hbN[bid * H_ + tid], nh);
                o_out[(t * B_ + bid) * H_ + tid] = nh;
                float teo = __ldcg(&teO[bid * H_ + tid]);
                __stcg(&teN[bid * H_ + tid], teo + sv * (sm[SM_SH + tid] - teo));
                float mv = 0.f;
                const float4* mr = (const float4*)(mod2h + tid * R_);
#pragma unroll
                for (int r = 0; r < 16; r++) {
                    float4 m4 = mr[r];
                    const float* su_ = &sm[SM_SU2 + 4 * r];
                    mv += m4.x*su_[0] + m4.y*su_[1] + m4.z*su_[2] + m4.w*su_[3];
                }
                __stcg(&g_mod[bid * H_ + tid], mv);
            }
        }
        grid_barrier();

        // ---- big phase (all blocks): tE/dU resident update + next z ----
        {
            float hn[8], ho[8], tev[8];
#pragma unroll
            for (int m = 0; m < 8; m++) {
                int j = lane + 32 * m;
                hn[m]  = __ldcg(&hbN[myb * H_ + j]);
                ho[m]  = __ldcg(&hbO[myb * H_ + j]);
                tev[m] = __ldcg(&teO[myb * H_ + j]);
            }
#pragma unroll
            for (int r = 0; r < ISUB; r++) {
                int i = i_grp * ISUB + r;
                if (i < H_) {
                    float nh_i  = __ldcg(&hbN[myb * H_ + i]);
                    float nte_i = __ldcg(&teN[myb * H_ + i]);
                    float mod_i = __ldcg(&g_mod[myb * H_ + i]);
                    float acc = 0.f;
                    int baseS = (w * ISUB + r) * H_ + lane;
                    int baseC = r * H_ + lane;
#pragma unroll
                    for (int m = 0; m < 8; m++) {
                        int o = 32 * m;
                        float tEo = sm[SM_TE + baseS + o];
                        float se  = sm[SM_SE + baseC + o];
                        float tEn = tEo + se * (fmaf(nh_i, tev[m], -nte_i * ho[m]) - tEo);
                        sm[SM_TE + baseS + o] = tEn;
                        float su_ = sm[SM_SU + baseC + o];
                        float dUo = dUr[r][m];
                        float dUn = dUo + su_ * (mod_i * tEn - dUo);
                        dUn = fmaxf(fminf(dUn, sm[SM_HI + baseC + o]), sm[SM_LO + baseC + o]);
                        dUr[r][m] = dUn;
                        acc = fmaf(sm[SM_RA + baseC + o] * dUn, hn[m], acc);
                    }
#pragma unroll
                    for (int o = 16; o > 0; o >>= 1) acc += __shfl_xor_sync(0xffffffffu, acc, o);
                    if (lane == 0) __stcg(&g_z[myb * H_ + i], acc);
                }
            }
        }
        if (t < T_ - 1) grid_barrier();
    }

    // ============ EPILOGUE ============
    __syncthreads();
    for (int idx = tid; idx < BSUB * ISUB * H_; idx += NTHR) {
        int row = idx >> 8;
        int wsub = row / ISUB, isub = row - wsub * ISUB;
        int i = i_grp * ISUB + isub;
        int b = b_grp * BSUB + wsub;
        int j = idx & 255;
        if (i < H_) o_tE[(b * H_ + i) * H_ + j] = sm[SM_TE + idx];
    }
#pragma unroll
    for (int r = 0; r < ISUB; r++) {
        int i = i_grp * ISUB + r;
        if (i < H_) {
#pragma unroll
            for (int m = 0; m < 8; m++)
                o_dU[(myb * H_ + i) * H_ + lane + 32 * m] = dUr[r][m];
        }
    }
    if (bid < B_ && tid < H_) {
        o_v[bid * H_ + tid]  = sm[SM_V + tid];
        o_h[bid * H_ + tid]  = __ldcg(&g_hbuf[bid * H_ + tid]);   // T even -> buffer 0
        o_te[bid * H_ + tid] = __ldcg(&g_tebuf[bid * H_ + tid]);
    }
}

extern "C" void kernel_launch(void* const* d_in, const int* in_sizes, int n_in,
                              void* d_out, int out_size) {
    cudaFuncSetAttribute(sgru_persistent, cudaFuncAttributeMaxDynamicSharedMemorySize, SM_BYTES);
    sgru_persistent<<<NBLK, NTHR, SM_BYTES>>>(
        (const float*)d_in[0],  (const float*)d_in[1],  (const float*)d_in[2],
        (const float*)d_in[3],  (const float*)d_in[4],  (const float*)d_in[5],
        (const float*)d_in[6],  (const float*)d_in[7],  (const float*)d_in[8],
        (const float*)d_in[9],  (const float*)d_in[10], (const float*)d_in[11],
        (const float*)d_in[12], (const float*)d_in[13], (const float*)d_in[14],
        (const float*)d_in[15], (const float*)d_in[16], (const float*)d_in[17],
        (const float*)d_in[18], (float*)d_out);
}

// round 4
// speedup vs baseline: 2.2055x; 2.2055x over previous
#include <cuda_runtime.h>
#include <math.h>
#include <stdint.h>

#define T_ 24
#define B_ 64
#define I_ 128
#define H_ 256
#define R_ 64
#define HR 320
#define NTHR 512
#define LN_EPS 1e-5f

// ---- smem float offsets ----
#define SM_TE   0        // 128*256 = 32768 (tE half: [li][j])
#define SM_H    32768    // 2*256 ping-pong h
#define SM_TEV  33280    // 2*256 ping-pong te
#define SM_Z    33792    // 2*256 ping-pong z
#define SM_V    34304    // 256
#define SM_MOD  34560    // 256
#define SM_WH   34816    // 320
#define SM_SV   35136    // 256
#define SM_U    35392    // 64
#define SM_RED  35456    // 64
#define SM_TOT  35520
#define SM_BYTES (SM_TOT*4)

// ---- global scratch ----
__device__ float  g_Wx[T_*B_*HR];
__device__ float2 g_hilo[H_*H_];
__device__ float  g_ra[H_*H_];
__device__ float  g_sU[H_*H_];
__device__ float  g_sE[H_*H_];
__device__ int    g_unif;
__device__ float  g_ra0, g_sU0, g_sE0;

__device__ __forceinline__ float sigmoidf(float x) { return 1.f / (1.f + expf(-x)); }

__device__ __forceinline__ uint32_t s2u(const void* p) {
    uint32_t a;
    asm("{ .reg .u64 t; cvta.to.shared.u64 t, %1; cvt.u32.u64 %0, t; }" : "=r"(a) : "l"(p));
    return a;
}
__device__ __forceinline__ uint32_t ctarank() {
    uint32_t r; asm("mov.u32 %0, %%cluster_ctarank;" : "=r"(r)); return r;
}
__device__ __forceinline__ void st_remote(uint32_t my_addr, uint32_t peer, float v) {
    uint32_t ra;
    asm volatile("mapa.shared::cluster.u32 %0, %1, %2;" : "=r"(ra) : "r"(my_addr), "r"(peer));
    asm volatile("st.shared::cluster.f32 [%0], %1;" :: "r"(ra), "f"(v) : "memory");
}
#define CLUSTER_SYNC() do { \
    asm volatile("barrier.cluster.arrive.aligned;" ::: "memory"); \
    asm volatile("barrier.cluster.wait.aligned;" ::: "memory"); } while (0)

// -------- init flag --------
__global__ void k_init() { g_unif = 1; }

// -------- per-(i,j) constants + uniformity detection --------
__global__ void k_prep(const float* __restrict__ alpha,
                       const float* __restrict__ tauU,
                       const float* __restrict__ tauE,
                       const float* __restrict__ h2h_w) {
    int idx = blockIdx.x * blockDim.x + threadIdx.x;   // 0..65535
    float a = alpha[idx], u = tauU[idx], e = tauE[idx];
    float ra = fmaxf(a, 0.f);
    g_ra[idx] = ra;
    g_sU[idx] = sigmoidf(u);
    g_sE[idx] = sigmoidf(e);
    float wv = h2h_w[idx];               // W_hh rows 0..255 == linear idx
    float inv = 1.f / (ra + 1e-8f);
    g_hilo[idx] = make_float2(fmaxf(1.f - wv, 0.f) * inv,
                              -fmaxf(1.f + wv, 0.f) * inv);
    bool eq = (a == alpha[0]) && (u == tauU[0]) && (e == tauE[0]);
    if (!eq) atomicAnd(&g_unif, 0);
    if (idx == 0) { g_ra0 = ra; g_sU0 = sigmoidf(u); g_sE0 = sigmoidf(e); }
}

// -------- Wx for all timesteps: LN(x_t @ x2h_w.T + x2h_b) --------
__global__ void k_wx(const float* __restrict__ x,
                     const float* __restrict__ w,
                     const float* __restrict__ bias,
                     const float* __restrict__ lng,
                     const float* __restrict__ lnb) {
    int tb = blockIdx.x;
    int k = threadIdx.x;               // 0..319
    __shared__ float sx[I_];
    __shared__ float red[20];
    if (k < I_) sx[k] = x[tb * I_ + k];
    __syncthreads();
    float acc = bias[k];
    const float4* wr = (const float4*)(w + k * I_);
#pragma unroll
    for (int m = 0; m < I_/4; m++) {
        float4 wv = wr[m];
        acc += wv.x*sx[4*m] + wv.y*sx[4*m+1] + wv.z*sx[4*m+2] + wv.w*sx[4*m+3];
    }
    float s = acc, s2 = acc*acc;
#pragma unroll
    for (int o = 16; o > 0; o >>= 1) {
        s  += __shfl_xor_sync(0xffffffffu, s,  o);
        s2 += __shfl_xor_sync(0xffffffffu, s2, o);
    }
    int wid = k >> 5, lane = k & 31;
    if (lane == 0) { red[wid] = s; red[10 + wid] = s2; }
    __syncthreads();
    if (wid == 0) {
        float a  = (lane < 10) ? red[lane] : 0.f;
        float b2 = (lane < 10) ? red[10 + lane] : 0.f;
#pragma unroll
        for (int o = 16; o > 0; o >>= 1) {
            a  += __shfl_xor_sync(0xffffffffu, a,  o);
            b2 += __shfl_xor_sync(0xffffffffu, b2, o);
        }
        if (lane == 0) { red[0] = a; red[10] = b2; }
    }
    __syncthreads();
    float mu  = red[0] * (1.f/HR);
    float inv = rsqrtf(red[10] * (1.f/HR) - mu*mu + LN_EPS);
    g_Wx[tb*HR + k] = (acc - mu) * inv * lng[k] + lnb[k];
}

// ================= main per-batch cluster kernel =================
template<bool UNIF>
__device__ __forceinline__ void run_all(
    float* sm, uint32_t smb, int b, int rank, int tid, int w, int lane,
    const float* __restrict__ h0,  const float* __restrict__ v0,
    const float* __restrict__ dU0, const float* __restrict__ te0,
    const float* __restrict__ tE0,
    const float* __restrict__ h2h_w, const float* __restrict__ h2h_b,
    const float* __restrict__ lnh_g, const float* __restrict__ lnh_b,
    const float* __restrict__ mod2h, const float* __restrict__ tau_v,
    float* __restrict__ outp)
{
    float* o_v   = outp;
    float* o_h   = outp + 16384;
    float* o_dU  = outp + 32768;
    float* o_te  = outp + 4227072;
    float* o_tE  = outp + 4243456;
    float* o_out = outp + 8437760;

    const uint32_t peer = rank ^ 1u;
    const int i0 = rank * 128;
    const float ra0 = g_ra0, sU0 = g_sU0, sE0 = g_sE0;

    // ---------- prologue ----------
    if (tid < H_) {
        sm[SM_SV + tid]  = sigmoidf(tau_v[tid]);
        sm[SM_H + tid]   = h0[b*H_ + tid];
        sm[SM_TEV + tid] = te0[b*H_ + tid];
        sm[SM_V + tid]   = v0[b*H_ + tid];
    }
    float dUr[8][8];
    {
        float h0j[8];
#pragma unroll
        for (int m = 0; m < 8; m++) h0j[m] = h0[b*H_ + lane + 32*m];
#pragma unroll
        for (int is = 0; is < 8; is++) {
            int li = w*8 + is;
            int i  = i0 + li;
            const float* drow = dU0 + (b*H_ + i)*H_ + lane;
            const float* trow = tE0 + (b*H_ + i)*H_ + lane;
            float acc = 0.f;
#pragma unroll
            for (int m = 0; m < 8; m++) {
                float d = drow[32*m];
                dUr[is][m] = d;
                sm[SM_TE + li*H_ + lane + 32*m] = trow[32*m];
                if (UNIF) acc = fmaf(d, h0j[m], acc);
                else      acc = fmaf(g_ra[i*H_ + lane + 32*m] * d, h0j[m], acc);
            }
#pragma unroll
            for (int o = 16; o > 0; o >>= 1) acc += __shfl_xor_sync(0xffffffffu, acc, o);
            if (lane == 0) {
                float zi = UNIF ? ra0 * acc : acc;
                sm[SM_Z + i] = zi;
                st_remote(smb + 4u*(SM_Z + i), peer, zi);
            }
        }
    }
    CLUSTER_SYNC();

    // ---------- time loop ----------
    for (int t = 0; t < T_; t++) {
        const int hO  = SM_H   + (t & 1)*H_;
        const int hN  = SM_H   + ((t+1) & 1)*H_;
        const int teO = SM_TEV + (t & 1)*H_;
        const int teN = SM_TEV + ((t+1) & 1)*H_;
        const int zR  = SM_Z   + (t & 1)*H_;
        const int zW  = SM_Z   + ((t+1) & 1)*H_;

        // -- Wh own k-half (160 outputs): warp w -> k = rank*160 + w*10 + q --
        {
            int kbase = rank*160 + w*10;
#pragma unroll
            for (int q = 0; q < 10; q++) {
                int k = kbase + q;
                const float* wr = h2h_w + k*H_ + lane;
                float acc = 0.f;
#pragma unroll
                for (int e = 0; e < 8; e++)
                    acc = fmaf(__ldg(wr + 32*e), sm[hO + lane + 32*e], acc);
#pragma unroll
                for (int o = 16; o > 0; o >>= 1) acc += __shfl_xor_sync(0xffffffffu, acc, o);
                if (lane == 0) {
                    float vv = acc + h2h_b[k];
                    sm[SM_WH + k] = vv;
                    st_remote(smb + 4u*(SM_WH + k), peer, vv);
                }
            }
        }
        CLUSTER_SYNC();   // sync A: full Wh visible in both CTAs

        // -- LN over 320 (redundant in both CTAs) --
        float val = (tid < HR) ? sm[SM_WH + tid] : 0.f;
        {
            float s = val, s2 = val*val;
#pragma unroll
            for (int o = 16; o > 0; o >>= 1) {
                s  += __shfl_xor_sync(0xffffffffu, s,  o);
                s2 += __shfl_xor_sync(0xffffffffu, s2, o);
            }
            if (lane == 0) { sm[SM_RED + w] = s; sm[SM_RED + 16 + w] = s2; }
        }
        __syncthreads();
        if (w == 0) {
            float a  = (lane < 16) ? sm[SM_RED + lane] : 0.f;
            float a2 = (lane < 16) ? sm[SM_RED + 16 + lane] : 0.f;
#pragma unroll
            for (int o = 16; o > 0; o >>= 1) {
                a  += __shfl_xor_sync(0xffffffffu, a,  o);
                a2 += __shfl_xor_sync(0xffffffffu, a2, o);
            }
            if (lane == 0) { sm[SM_RED + 32] = a; sm[SM_RED + 33] = a2; }
        }
        __syncthreads();
        float mu  = sm[SM_RED + 32] * (1.f/HR);
        float inv = rsqrtf(sm[SM_RED + 33] * (1.f/HR) - mu*mu + LN_EPS);
        float whv = 0.f, wxv = 0.f;
        if (tid < HR) {
            whv = (val - mu) * inv * lnh_g[tid] + lnh_b[tid];
            wxv = g_Wx[(t*B_ + b)*HR + tid];
            if (tid >= H_) sm[SM_U + tid - H_] = fmaxf(wxv + whv, 0.f);
        }
        __syncthreads();
        if (tid < H_) {
            float sv = sm[SM_SV + tid];
            float dv = wxv + whv + sm[zR + tid];
            float vo = sm[SM_V + tid];
            float vn = fmaf(sv, dv - vo, vo);
            sm[SM_V + tid] = vn;
            float nh = fmaxf(vn, 0.f);
            sm[hN + tid] = nh;
            float teo = sm[teO + tid];
            sm[teN + tid] = fmaf(sv, sm[hO + tid] - teo, teo);
            if ((tid >> 7) == rank) {
                o_out[(t*B_ + b)*H_ + tid] = nh;
                float mv = 0.f;
                const float4* mr = (const float4*)(mod2h + tid*R_);
#pragma unroll
                for (int r = 0; r < 16; r++) {
                    float4 m4 = __ldg(mr + r);
                    mv += m4.x*sm[SM_U + 4*r] + m4.y*sm[SM_U + 4*r+1]
                        + m4.z*sm[SM_U + 4*r+2] + m4.w*sm[SM_U + 4*r+3];
                }
                sm[SM_MOD + tid] = mv;
            }
        }
        __syncthreads();

        // -- big phase: own i-half tE/dU update + next z --
        {
            float hoj[8], tej[8], hnj[8];
#pragma unroll
            for (int m = 0; m < 8; m++) {
                hoj[m] = sm[hO + lane + 32*m];
                tej[m] = sm[teO + lane + 32*m];
                hnj[m] = sm[hN + lane + 32*m];
            }
#pragma unroll
            for (int is = 0; is < 8; is++) {
                int li = w*8 + is;
                int i  = i0 + li;
                float nh_i  = sm[hN + i];
                float nte_i = sm[teN + i];
                float mod_i = sm[SM_MOD + i];
                float acc = 0.f;
#pragma unroll
                for (int m = 0; m < 8; m++) {
                    int e = i*H_ + lane + 32*m;
                    float2 hl = __ldg(&g_hilo[e]);
                    float se = UNIF ? sE0 : __ldg(&g_sE[e]);
                    float su = UNIF ? sU0 : __ldg(&g_sU[e]);
                    int sidx = SM_TE + li*H_ + lane + 32*m;
                    float tEo = sm[sidx];
                    float t1  = nte_i * hoj[m];
                    float a   = fmaf(nh_i, tej[m], -t1);
                    float tEn = fmaf(se, a - tEo, tEo);
                    sm[sidx] = tEn;
                    float dUo = dUr[is][m];
                    float d2  = fmaf(mod_i, tEn, -dUo);
                    float dUn = fmaf(su, d2, dUo);
                    dUn = fmaxf(fminf(dUn, hl.x), hl.y);
                    dUr[is][m] = dUn;
                    if (UNIF) acc = fmaf(dUn, hnj[m], acc);
                    else      acc = fmaf(__ldg(&g_ra[e]) * dUn, hnj[m], acc);
                }
#pragma unroll
                for (int o = 16; o > 0; o >>= 1) acc += __shfl_xor_sync(0xffffffffu, acc, o);
                if (lane == 0) {
                    float zi = UNIF ? ra0 * acc : acc;
                    sm[zW + i] = zi;
                    st_remote(smb + 4u*(zW + i), peer, zi);
                }
            }
        }
        CLUSTER_SYNC();   // sync B: z exchanged; peer may proceed
    }

    // ---------- epilogue ----------
#pragma unroll
    for (int is = 0; is < 8; is++) {
        int li = w*8 + is;
        int i  = i0 + li;
        float* drow = o_dU + (size_t)(b*H_ + i)*H_ + lane;
        float* trow = o_tE + (size_t)(b*H_ + i)*H_ + lane;
#pragma unroll
        for (int m = 0; m < 8; m++) {
            drow[32*m] = dUr[is][m];
            trow[32*m] = sm[SM_TE + li*H_ + lane + 32*m];
        }
    }
    if (tid < 128) {
        int idx = i0 + tid;                  // rank-half of the vectors
        o_v[b*H_ + idx]  = sm[SM_V + idx];
        o_h[b*H_ + idx]  = sm[SM_H + idx];   // T even -> final in buffer 0
        o_te[b*H_ + idx] = sm[SM_TEV + idx];
    }
}

__global__ void __launch_bounds__(NTHR, 1) __cluster_dims__(2, 1, 1)
sgru_cluster(const float* __restrict__ h0,  const float* __restrict__ v0,
             const float* __restrict__ dU0, const float* __restrict__ te0,
             const float* __restrict__ tE0,
             const float* __restrict__ h2h_w, const float* __restrict__ h2h_b,
             const float* __restrict__ lnh_g, const float* __restrict__ lnh_b,
             const float* __restrict__ mod2h, const float* __restrict__ tau_v,
             float* __restrict__ outp)
{
    extern __shared__ float sm[];
    const int tid  = threadIdx.x;
    const int w    = tid >> 5;
    const int lane = tid & 31;
    const int b    = blockIdx.x >> 1;
    const int rank = (int)ctarank();
    const uint32_t smb = s2u(sm);

    if (g_unif) run_all<true >(sm, smb, b, rank, tid, w, lane, h0, v0, dU0, te0, tE0,
                               h2h_w, h2h_b, lnh_g, lnh_b, mod2h, tau_v, outp);
    else        run_all<false>(sm, smb, b, rank, tid, w, lane, h0, v0, dU0, te0, tE0,
                               h2h_w, h2h_b, lnh_g, lnh_b, mod2h, tau_v, outp);
}

extern "C" void kernel_launch(void* const* d_in, const int* in_sizes, int n_in,
                              void* d_out, int out_size) {
    const float* x      = (const float*)d_in[0];
    const float* h0     = (const float*)d_in[1];
    const float* v0     = (const float*)d_in[2];
    const float* dU0    = (const float*)d_in[3];
    const float* te0    = (const float*)d_in[4];
    const float* tE0    = (const float*)d_in[5];
    const float* x2h_w  = (const float*)d_in[6];
    const float* x2h_b  = (const float*)d_in[7];
    const float* h2h_w  = (const float*)d_in[8];
    const float* h2h_b  = (const float*)d_in[9];
    const float* lnx_g  = (const float*)d_in[10];
    const float* lnx_b  = (const float*)d_in[11];
    const float* lnh_g  = (const float*)d_in[12];
    const float* lnh_b  = (const float*)d_in[13];
    const float* alpha  = (const float*)d_in[14];
    const float* mod2h  = (const float*)d_in[15];
    const float* tau_v  = (const float*)d_in[16];
    const float* tau_U  = (const float*)d_in[17];
    const float* tau_E  = (const float*)d_in[18];

    static int smem_set = 0;
    if (!smem_set) {
        cudaFuncSetAttribute(sgru_cluster, cudaFuncAttributeMaxDynamicSharedMemorySize, SM_BYTES);
        smem_set = 1;
    }

    k_init<<<1, 1>>>();
    k_prep<<<H_*H_/256, 256>>>(alpha, tau_U, tau_E, h2h_w);
    k_wx<<<T_*B_, HR>>>(x, x2h_w, x2h_b, lnx_g, lnx_b);
    sgru_cluster<<<2*B_, NTHR, SM_BYTES>>>(h0, v0, dU0, te0, tE0,
                                           h2h_w, h2h_b, lnh_g, lnh_b,
                                           mod2h, tau_v, (float*)d_out);
}

// round 5
// speedup vs baseline: 2.6440x; 1.1988x over previous
#include <cuda_runtime.h>
#include <math.h>
#include <stdint.h>

#define T_ 24
#define B_ 64
#define I_ 128
#define H_ 256
#define R_ 64
#define HR 320
#define NTHR 512
#define LN_EPS 1e-5f

// ---- smem float offsets ----
#define SM_TE   0        // 128 rows * 128 float2 = 32768 floats
#define SM_H    32768    // 2*256 ping-pong h
#define SM_TEV  33280    // 2*256 ping-pong te
#define SM_Z    33792    // 2*256 ping-pong z
#define SM_V    34304    // 256
#define SM_MOD  34560    // 256
#define SM_WH   34816    // 320
#define SM_SV   35136    // 256
#define SM_U    35392    // 64
#define SM_RED  35456    // 64
#define SM_TOT  35520
#define SM_BYTES (SM_TOT*4)

// ---- global scratch ----
__device__ float  g_Wx[T_*B_*HR];
__device__ float2 g_hilo[H_*H_];
__device__ float  g_ra[H_*H_];
__device__ float  g_sU[H_*H_];
__device__ float  g_sE[H_*H_];
__device__ int    g_unif;
__device__ int    g_munif;
__device__ int    g_bmin_bits;
__device__ float  g_ra0, g_sU0, g_sE0, g_m2h0;

typedef unsigned long long u64;

__device__ __forceinline__ float sigmoidf(float x) { return 1.f / (1.f + expf(-x)); }

__device__ __forceinline__ u64 pk2(float lo, float hi) {
    u64 r; asm("mov.b64 %0, {%1, %2};" : "=l"(r) : "f"(lo), "f"(hi)); return r;
}
__device__ __forceinline__ float2 upk2(u64 v) {
    float2 r; asm("mov.b64 {%0, %1}, %2;" : "=f"(r.x), "=f"(r.y) : "l"(v)); return r;
}
__device__ __forceinline__ u64 fma2(u64 a, u64 b, u64 c) {
    u64 r; asm("fma.rn.f32x2 %0, %1, %2, %3;" : "=l"(r) : "l"(a), "l"(b), "l"(c)); return r;
}
__device__ __forceinline__ u64 mul2(u64 a, u64 b) {
    u64 r; asm("mul.rn.f32x2 %0, %1, %2;" : "=l"(r) : "l"(a), "l"(b)); return r;
}
__device__ __forceinline__ u64 pkf2(float2 v) { return pk2(v.x, v.y); }

__device__ __forceinline__ uint32_t s2u(const void* p) {
    uint32_t a;
    asm("{ .reg .u64 t; cvta.to.shared.u64 t, %1; cvt.u32.u64 %0, t; }" : "=r"(a) : "l"(p));
    return a;
}
__device__ __forceinline__ uint32_t ctarank() {
    uint32_t r; asm("mov.u32 %0, %%cluster_ctarank;" : "=r"(r)); return r;
}
__device__ __forceinline__ void st_remote(uint32_t my_addr, uint32_t peer, float v) {
    uint32_t ra;
    asm volatile("mapa.shared::cluster.u32 %0, %1, %2;" : "=r"(ra) : "r"(my_addr), "r"(peer));
    asm volatile("st.shared::cluster.f32 [%0], %1;" :: "r"(ra), "f"(v) : "memory");
}
#define CLUSTER_SYNC() do { \
    asm volatile("barrier.cluster.arrive.aligned;" ::: "memory"); \
    asm volatile("barrier.cluster.wait.aligned;" ::: "memory"); } while (0)

// -------- init flags --------
__global__ void k_init() { g_unif = 1; g_munif = 1; g_bmin_bits = 0x7f7fffff; }

// -------- per-(i,j) constants + uniformity detection + bmin --------
__global__ void k_prep(const float* __restrict__ alpha,
                       const float* __restrict__ tauU,
                       const float* __restrict__ tauE,
                       const float* __restrict__ h2h_w,
                       const float* __restrict__ mod2h) {
    int idx = blockIdx.x * blockDim.x + threadIdx.x;   // 0..65535
    float a = alpha[idx], u = tauU[idx], e = tauE[idx];
    float ra = fmaxf(a, 0.f);
    g_ra[idx] = ra;
    g_sU[idx] = sigmoidf(u);
    g_sE[idx] = sigmoidf(e);
    float wv = h2h_w[idx];
    float den = ra + 1e-8f;
    float hi = fmaxf(1.f - wv, 0.f) / den;
    float lo = -fmaxf(1.f + wv, 0.f) / den;
    g_hilo[idx] = make_float2(hi, lo);
    float bnd = fminf(hi, -lo);            // >= 0
    atomicMin(&g_bmin_bits, __float_as_int(bnd));
    bool eq = (a == alpha[0]) && (u == tauU[0]) && (e == tauE[0]);
    if (!eq) atomicAnd(&g_unif, 0);
    if (idx < H_ * R_) {
        if (mod2h[idx] != mod2h[0]) atomicAnd(&g_munif, 0);
    }
    if (idx == 0) {
        g_ra0 = ra; g_sU0 = sigmoidf(u); g_sE0 = sigmoidf(e); g_m2h0 = mod2h[0];
    }
}

// -------- Wx for all timesteps: LN(x_t @ x2h_w.T + x2h_b) --------
__global__ void k_wx(const float* __restrict__ x,
                     const float* __restrict__ w,
                     const float* __restrict__ bias,
                     const float* __restrict__ lng,
                     const float* __restrict__ lnb) {
    int tb = blockIdx.x;
    int k = threadIdx.x;               // 0..319
    __shared__ float sx[I_];
    __shared__ float red[20];
    if (k < I_) sx[k] = x[tb * I_ + k];
    __syncthreads();
    float acc = bias[k];
    const float4* wr = (const float4*)(w + k * I_);
#pragma unroll
    for (int m = 0; m < I_/4; m++) {
        float4 wv = wr[m];
        acc += wv.x*sx[4*m] + wv.y*sx[4*m+1] + wv.z*sx[4*m+2] + wv.w*sx[4*m+3];
    }
    float s = acc, s2 = acc*acc;
#pragma unroll
    for (int o = 16; o > 0; o >>= 1) {
        s  += __shfl_xor_sync(0xffffffffu, s,  o);
        s2 += __shfl_xor_sync(0xffffffffu, s2, o);
    }
    int wid = k >> 5, lane = k & 31;
    if (lane == 0) { red[wid] = s; red[10 + wid] = s2; }
    __syncthreads();
    if (wid == 0) {
        float a  = (lane < 10) ? red[lane] : 0.f;
        float b2 = (lane < 10) ? red[10 + lane] : 0.f;
#pragma unroll
        for (int o = 16; o > 0; o >>= 1) {
            a  += __shfl_xor_sync(0xffffffffu, a,  o);
            b2 += __shfl_xor_sync(0xffffffffu, b2, o);
        }
        if (lane == 0) { red[0] = a; red[10] = b2; }
    }
    __syncthreads();
    float mu  = red[0] * (1.f/HR);
    float inv = rsqrtf(red[10] * (1.f/HR) - mu*mu + LN_EPS);
    g_Wx[tb*HR + k] = (acc - mu) * inv * lng[k] + lnb[k];
}

// ================= main per-batch cluster kernel =================
template<bool UNIF>
__device__ __forceinline__ void run_all(
    float* sm, uint32_t smb, int b, int rank, int tid, int w, int lane,
    const float* __restrict__ h0,  const float* __restrict__ v0,
    const float* __restrict__ dU0, const float* __restrict__ te0,
    const float* __restrict__ tE0,
    const float* __restrict__ h2h_w, const float* __restrict__ h2h_b,
    const float* __restrict__ lnh_g, const float* __restrict__ lnh_b,
    const float* __restrict__ mod2h, const float* __restrict__ tau_v,
    float* __restrict__ outp)
{
    float* o_v   = outp;
    float* o_h   = outp + 16384;
    float* o_dU  = outp + 32768;
    float* o_te  = outp + 4227072;
    float* o_tE  = outp + 4243456;
    float* o_out = outp + 8437760;

    const uint32_t peer = rank ^ 1u;
    const int i0 = rank * 128;
    const bool munif = (g_munif != 0);
    const float m2h0 = g_m2h0;
    const float ra0 = g_ra0, sU0 = g_sU0, sE0 = g_sE0;
    const float bmin = __int_as_float(g_bmin_bits);
    const u64 c_sE2  = pk2(sE0, sE0);
    const u64 c_osE2 = pk2(1.f - sE0, 1.f - sE0);
    const u64 c_osU2 = pk2(1.f - sU0, 1.f - sU0);
    float2* smTE2 = (float2*)sm;   // SM_TE == 0

    // ---------- prologue ----------
    if (tid < H_) {
        sm[SM_SV + tid]  = sigmoidf(tau_v[tid]);
        sm[SM_H + tid]   = h0[b*H_ + tid];
        sm[SM_TEV + tid] = te0[b*H_ + tid];
        sm[SM_V + tid]   = v0[b*H_ + tid];
    }
    u64 dUr2[8][4];
    {
        const float2* h0p = (const float2*)(h0 + b*H_);
        u64 h0j2[4];
#pragma unroll
        for (int m = 0; m < 4; m++) h0j2[m] = pkf2(h0p[lane + 32*m]);
#pragma unroll
        for (int is = 0; is < 8; is++) {
            int li = w*8 + is;
            int i  = i0 + li;
            const float2* drow = (const float2*)(dU0 + (size_t)(b*H_ + i)*H_);
            const float2* trow = (const float2*)(tE0 + (size_t)(b*H_ + i)*H_);
            u64 acc2 = pk2(0.f, 0.f);
#pragma unroll
            for (int m = 0; m < 4; m++) {
                int p = lane + 32*m;
                float2 d = drow[p];
                smTE2[li*128 + p] = trow[p];
                u64 dv = pkf2(d);
                dUr2[is][m] = dv;
                if (UNIF) acc2 = fma2(dv, h0j2[m], acc2);
                else {
                    const float2* rap = (const float2*)(g_ra + (size_t)i*H_);
                    acc2 = fma2(mul2(pkf2(rap[p]), dv), h0j2[m], acc2);
                }
            }
            float2 af = upk2(acc2);
            float acc = af.x + af.y;
#pragma unroll
            for (int o = 16; o > 0; o >>= 1) acc += __shfl_xor_sync(0xffffffffu, acc, o);
            if (lane == 0) {
                float zi = UNIF ? ra0 * acc : acc;
                sm[SM_Z + i] = zi;
                st_remote(smb + 4u*(SM_Z + i), peer, zi);
            }
        }
    }
    CLUSTER_SYNC();

    // ---------- time loop ----------
    for (int t = 0; t < T_; t++) {
        const int hO  = SM_H   + (t & 1)*H_;
        const int hN  = SM_H   + ((t+1) & 1)*H_;
        const int teO = SM_TEV + (t & 1)*H_;
        const int teN = SM_TEV + ((t+1) & 1)*H_;
        const int zR  = SM_Z   + (t & 1)*H_;
        const int zW  = SM_Z   + ((t+1) & 1)*H_;

        // -- Wh own k-half (160 rows): warp w -> k = rank*160 + w*10 + q --
        {
            int kbase = rank*160 + w*10;
            const float2* h2 = (const float2*)&sm[hO];
#pragma unroll
            for (int q = 0; q < 10; q++) {
                int k = kbase + q;
                const float2* wr = (const float2*)(h2h_w + (size_t)k*H_);
                u64 acc2 = pk2(0.f, 0.f);
#pragma unroll
                for (int e = 0; e < 4; e++) {
                    int p = lane + 32*e;
                    acc2 = fma2(pkf2(__ldg(&wr[p])), pkf2(h2[p]), acc2);
                }
                float2 af = upk2(acc2);
                float acc = af.x + af.y;
#pragma unroll
                for (int o = 16; o > 0; o >>= 1) acc += __shfl_xor_sync(0xffffffffu, acc, o);
                if (lane == 0) {
                    float vv = acc + h2h_b[k];
                    sm[SM_WH + k] = vv;
                    st_remote(smb + 4u*(SM_WH + k), peer, vv);
                }
            }
        }
        CLUSTER_SYNC();   // sync A: full Wh visible in both CTAs

        // -- LN over 320 --
        float val = (tid < HR) ? sm[SM_WH + tid] : 0.f;
        {
            float s = val, s2 = val*val;
#pragma unroll
            for (int o = 16; o > 0; o >>= 1) {
                s  += __shfl_xor_sync(0xffffffffu, s,  o);
                s2 += __shfl_xor_sync(0xffffffffu, s2, o);
            }
            if (lane == 0) { sm[SM_RED + w] = s; sm[SM_RED + 16 + w] = s2; }
        }
        __syncthreads();
        if (w == 0) {
            float a  = (lane < 16) ? sm[SM_RED + lane] : 0.f;
            float a2 = (lane < 16) ? sm[SM_RED + 16 + lane] : 0.f;
#pragma unroll
            for (int o = 16; o > 0; o >>= 1) {
                a  += __shfl_xor_sync(0xffffffffu, a,  o);
                a2 += __shfl_xor_sync(0xffffffffu, a2, o);
            }
            if (lane == 0) { sm[SM_RED + 32] = a; sm[SM_RED + 33] = a2; }
        }
        __syncthreads();
        float mu  = sm[SM_RED + 32] * (1.f/HR);
        float inv = rsqrtf(sm[SM_RED + 33] * (1.f/HR) - mu*mu + LN_EPS);
        float whv = 0.f, wxv = 0.f;
        if (tid < HR) {
            whv = (val - mu) * inv * lnh_g[tid] + lnh_b[tid];
            wxv = g_Wx[(t*B_ + b)*HR + tid];
            if (tid >= H_) sm[SM_U + tid - H_] = fmaxf(wxv + whv, 0.f);
        }
        __syncthreads();
        if (munif && w == 0) {
            float u = sm[SM_U + lane] + sm[SM_U + 32 + lane];
#pragma unroll
            for (int o = 16; o > 0; o >>= 1) u += __shfl_xor_sync(0xffffffffu, u, o);
            if (lane == 0) sm[SM_RED + 40] = u * m2h0;
        }
        __syncthreads();
        if (tid < H_) {
            float sv = sm[SM_SV + tid];
            float dv = wxv + whv + sm[zR + tid];
            float vo = sm[SM_V + tid];
            float vn = (1.f - sv) * vo + sv * dv;
            sm[SM_V + tid] = vn;
            float nh = fmaxf(vn, 0.f);
            sm[hN + tid] = nh;
            float teo = sm[teO + tid];
            sm[teN + tid] = (1.f - sv) * teo + sv * sm[hO + tid];
            if ((tid >> 7) == rank) o_out[(t*B_ + b)*H_ + tid] = nh;
            float mv;
            if (munif) {
                mv = sm[SM_RED + 40];
            } else {
                mv = 0.f;
                const float4* mr = (const float4*)(mod2h + tid*R_);
#pragma unroll
                for (int r = 0; r < 16; r++) {
                    float4 m4 = __ldg(mr + r);
                    mv += m4.x*sm[SM_U + 4*r] + m4.y*sm[SM_U + 4*r+1]
                        + m4.z*sm[SM_U + 4*r+2] + m4.w*sm[SM_U + 4*r+3];
                }
            }
            sm[SM_MOD + tid] = mv;
        }
        __syncthreads();

        // -- big phase: own i-half tE/dU update + next z --
        {
            u64 hoj2[4], tej2[4], hnj2[4];
            const float2* hOp = (const float2*)&sm[hO];
            const float2* teOp = (const float2*)&sm[teO];
            const float2* hNp = (const float2*)&sm[hN];
#pragma unroll
            for (int m = 0; m < 4; m++) {
                int p = lane + 32*m;
                hoj2[m] = pkf2(hOp[p]);
                tej2[m] = pkf2(teOp[p]);
                hnj2[m] = pkf2(hNp[p]);
            }
#pragma unroll
            for (int is = 0; is < 8; is++) {
                int li = w*8 + is;
                int i  = i0 + li;
                float nh_i  = sm[hN + i];
                float nte_i = sm[teN + i];
                float mod_i = sm[SM_MOD + i];
                u64 nh2   = pk2(nh_i, nh_i);
                u64 mnte2 = pk2(-nte_i, -nte_i);
                u64 acc2  = pk2(0.f, 0.f);
                if (UNIF) {
                    float cm = sU0 * mod_i;
                    u64 cm2 = pk2(cm, cm);
#pragma unroll
                    for (int m = 0; m < 4; m++) {
                        int idx = li*128 + lane + 32*m;
                        u64 tE2 = pkf2(smTE2[idx]);
                        u64 a   = fma2(mnte2, hoj2[m], mul2(nh2, tej2[m]));
                        u64 tEn = fma2(c_sE2, a, mul2(c_osE2, tE2));
                        smTE2[idx] = upk2(tEn);
                        u64 dUn = fma2(c_osU2, dUr2[is][m], mul2(cm2, tEn));
                        float2 dv = upk2(dUn);
                        if (fmaxf(fabsf(dv.x), fabsf(dv.y)) > bmin) {   // rare exact clamp
                            int j0 = (i << 8) + 2*(lane + 32*m);
                            float2 hl0 = __ldg(&g_hilo[j0]);
                            float2 hl1 = __ldg(&g_hilo[j0 + 1]);
                            dv.x = fmaxf(fminf(dv.x, hl0.x), hl0.y);
                            dv.y = fmaxf(fminf(dv.y, hl1.x), hl1.y);
                            dUn = pk2(dv.x, dv.y);
                        }
                        dUr2[is][m] = dUn;
                        acc2 = fma2(dUn, hnj2[m], acc2);
                    }
                } else {
#pragma unroll
                    for (int m = 0; m < 4; m++) {
                        int idx = li*128 + lane + 32*m;
                        int p = lane + 32*m;
                        int j0 = (i << 8) + 2*p;
                        float2 tE2 = smTE2[idx];
                        float2 se2 = *(const float2*)(g_sE + j0);
                        float2 su2 = *(const float2*)(g_sU + j0);
                        float2 ra2 = *(const float2*)(g_ra + j0);
                        float2 ho = upk2(hoj2[m]), te = upk2(tej2[m]), hn = upk2(hnj2[m]);
                        float2 dUo = upk2(dUr2[is][m]);
                        float ax = nh_i*te.x - nte_i*ho.x;
                        float ay = nh_i*te.y - nte_i*ho.y;
                        float tEnx = (1.f - se2.x)*tE2.x + se2.x*ax;
                        float tEny = (1.f - se2.y)*tE2.y + se2.y*ay;
                        smTE2[idx] = make_float2(tEnx, tEny);
                        float dUx = (1.f - su2.x)*dUo.x + su2.x*mod_i*tEnx;
                        float dUy = (1.f - su2.y)*dUo.y + su2.y*mod_i*tEny;
                        float2 hl0 = __ldg(&g_hilo[j0]);
                        float2 hl1 = __ldg(&g_hilo[j0 + 1]);
                        dUx = fmaxf(fminf(dUx, hl0.x), hl0.y);
                        dUy = fmaxf(fminf(dUy, hl1.x), hl1.y);
                        dUr2[is][m] = pk2(dUx, dUy);
                        acc2 = fma2(pk2(ra2.x*dUx, ra2.y*dUy), hnj2[m], acc2);
                    }
                }
                float2 af = upk2(acc2);
                float acc = af.x + af.y;
#pragma unroll
                for (int o = 16; o > 0; o >>= 1) acc += __shfl_xor_sync(0xffffffffu, acc, o);
                if (lane == 0) {
                    float zi = UNIF ? ra0 * acc : acc;
                    sm[zW + i] = zi;
                    st_remote(smb + 4u*(zW + i), peer, zi);
                }
            }
        }
        CLUSTER_SYNC();   // sync B: z exchanged
    }

    // ---------- epilogue ----------
#pragma unroll
    for (int is = 0; is < 8; is++) {
        int li = w*8 + is;
        int i  = i0 + li;
        float2* drow = (float2*)(o_dU + (size_t)(b*H_ + i)*H_);
        float2* trow = (float2*)(o_tE + (size_t)(b*H_ + i)*H_);
#pragma unroll
        for (int m = 0; m < 4; m++) {
            int p = lane + 32*m;
            drow[p] = upk2(dUr2[is][m]);
            trow[p] = smTE2[li*128 + p];
        }
    }
    if (tid < 128) {
        int idx = i0 + tid;
        o_v[b*H_ + idx]  = sm[SM_V + idx];
        o_h[b*H_ + idx]  = sm[SM_H + idx];    // T even -> final in buffer 0
        o_te[b*H_ + idx] = sm[SM_TEV + idx];
    }
}

__global__ void __launch_bounds__(NTHR, 1) __cluster_dims__(2, 1, 1)
sgru_cluster(const float* __restrict__ h0,  const float* __restrict__ v0,
             const float* __restrict__ dU0, const float* __restrict__ te0,
             const float* __restrict__ tE0,
             const float* __restrict__ h2h_w, const float* __restrict__ h2h_b,
             const float* __restrict__ lnh_g, const float* __restrict__ lnh_b,
             const float* __restrict__ mod2h, const float* __restrict__ tau_v,
             float* __restrict__ outp)
{
    extern __shared__ float sm[];
    const int tid  = threadIdx.x;
    const int w    = tid >> 5;
    const int lane = tid & 31;
    const int b    = blockIdx.x >> 1;
    const int rank = (int)ctarank();
    const uint32_t smb = s2u(sm);

    if (g_unif) run_all<true >(sm, smb, b, rank, tid, w, lane, h0, v0, dU0, te0, tE0,
                               h2h_w, h2h_b, lnh_g, lnh_b, mod2h, tau_v, outp);
    else        run_all<false>(sm, smb, b, rank, tid, w, lane, h0, v0, dU0, te0, tE0,
                               h2h_w, h2h_b, lnh_g, lnh_b, mod2h, tau_v, outp);
}

extern "C" void kernel_launch(void* const* d_in, const int* in_sizes, int n_in,
                              void* d_out, int out_size) {
    const float* x      = (const float*)d_in[0];
    const float* h0     = (const float*)d_in[1];
    const float* v0     = (const float*)d_in[2];
    const float* dU0    = (const float*)d_in[3];
    const float* te0    = (const float*)d_in[4];
    const float* tE0    = (const float*)d_in[5];
    const float* x2h_w  = (const float*)d_in[6];
    const float* x2h_b  = (const float*)d_in[7];
    const float* h2h_w  = (const float*)d_in[8];
    const float* h2h_b  = (const float*)d_in[9];
    const float* lnx_g  = (const float*)d_in[10];
    const float* lnx_b  = (const float*)d_in[11];
    const float* lnh_g  = (const float*)d_in[12];
    const float* lnh_b  = (const float*)d_in[13];
    const float* alpha  = (const float*)d_in[14];
    const float* mod2h  = (const float*)d_in[15];
    const float* tau_v  = (const float*)d_in[16];
    const float* tau_U  = (const float*)d_in[17];
    const float* tau_E  = (const float*)d_in[18];

    static int smem_set = 0;
    if (!smem_set) {
        cudaFuncSetAttribute(sgru_cluster, cudaFuncAttributeMaxDynamicSharedMemorySize, SM_BYTES);
        smem_set = 1;
    }

    k_init<<<1, 1>>>();
    k_prep<<<H_*H_/256, 256>>>(alpha, tau_U, tau_E, h2h_w, mod2h);
    k_wx<<<T_*B_, HR>>>(x, x2h_w, x2h_b, lnx_g, lnx_b);
    sgru_cluster<<<2*B_, NTHR, SM_BYTES>>>(h0, v0, dU0, te0, tE0,
                                           h2h_w, h2h_b, lnh_g, lnh_b,
                                           mod2h, tau_v, (float*)d_out);
}